// round 1
// baseline (speedup 1.0000x reference)
#include <cuda_runtime.h>

namespace {
constexpr int Bsz    = 16384;
constexpr int Ncap   = 32;
constexpr int Din    = 128;
constexpr int Dout   = 256;
constexpr int RITERS = 3;

// shared memory layout (float offsets)
constexpr int OFF_W    = 0;                  // 32*16*32*2 = 32768 (W fragments, tf32)
constexpr int OFF_A    = OFF_W + 32768;      // 64 slots * 132 = 8448 (A fragments)
constexpr int OFF_BIAS = OFF_A + 64 * 132;   // 256
constexpr int OFF_NRM  = OFF_BIAS + 256;     // [2][32][4] = 256
constexpr int OFF_INV  = OFF_NRM + 256;      // 64
constexpr int OFF_BIJ  = OFF_INV + 64;       // 64
constexpr int OFF_C    = OFF_BIJ + 64;       // 64
constexpr int OFF_S    = OFF_C + 64;         // [2][256] = 512
constexpr int OFF_V    = OFF_S + 512;        // 512
constexpr int OFF_SQP  = OFF_V + 512;        // [8][2] = 16
constexpr int OFF_SC   = OFF_SQP + 16;       // 4
constexpr int OFF_AGR  = OFF_SC + 4;         // [2][32][4] = 256
constexpr int SMEM_FLOATS = OFF_AGR + 256;
constexpr int SMEM_BYTES  = SMEM_FLOATS * 4; // ~173 KB
}

__device__ __forceinline__ float to_tf32(float x) {
    float y;
    asm("cvt.rna.tf32.f32 %0, %1;" : "=f"(y) : "f"(x));
    return y;
}

__device__ __forceinline__ void mma_tf32(float* c, const float4 a, const float2 b) {
    asm volatile(
        "mma.sync.aligned.m16n8k8.row.col.f32.tf32.tf32.f32 "
        "{%0,%1,%2,%3}, {%4,%5,%6,%7}, {%8,%9}, {%0,%1,%2,%3};\n"
        : "+f"(c[0]), "+f"(c[1]), "+f"(c[2]), "+f"(c[3])
        : "r"(__float_as_uint(a.x)), "r"(__float_as_uint(a.y)),
          "r"(__float_as_uint(a.z)), "r"(__float_as_uint(a.w)),
          "r"(__float_as_uint(b.x)), "r"(__float_as_uint(b.y)));
}

__global__ void __launch_bounds__(256, 1)
dyr_agg_kernel(const float* __restrict__ embeds,
               const float* __restrict__ weights,
               const float* __restrict__ Wg,
               const float* __restrict__ bg,
               float* __restrict__ out)
{
    extern __shared__ float sm[];
    const int tid  = threadIdx.x;
    const int lane = tid & 31;
    const int w    = tid >> 5;     // warp 0..7
    const int cg   = w & 3;        // column group: 64 cols at cg*64
    const int rg   = w >> 2;       // row group (= which batch of the pair)
    const int qr   = lane >> 2;    // 0..7
    const int qc   = lane & 3;     // 0..3

    // ---- stage W into fragment-permuted tf32 layout (once per CTA) ----
    // slot idx: nt(32) * 16 ks * 32 lanes; each slot holds {b0,b1} for m16n8k8.
    for (int idx = tid; idx < 32 * 16 * 32; idx += 256) {
        int nt = idx >> 9;
        int ks = (idx >> 5) & 15;
        int ln = idx & 31;
        int k0 = ks * 8 + (ln & 3);
        int n  = nt * 8 + (ln >> 2);
        sm[OFF_W + idx * 2 + 0] = to_tf32(Wg[k0 * Dout + n]);
        sm[OFF_W + idx * 2 + 1] = to_tf32(Wg[(k0 + 4) * Dout + n]);
    }
    if (tid < Dout) sm[OFF_BIAS + tid] = bg[tid];
    __syncthreads();

    float* out_poses = out;
    float* out_c     = out + (size_t)Bsz * Dout;

    for (int unit = blockIdx.x; unit < Bsz / 2; unit += gridDim.x) {
        const int b0 = unit * 2;
        __syncthreads();  // previous unit's consumers are done before restaging

        // ---- stage A (2 batches = 64 rows x 128 cols) into fragment layout ----
        const float4* eg = (const float4*)(embeds + (size_t)b0 * Ncap * Din);
        #pragma unroll
        for (int t = 0; t < 8; t++) {
            int i = tid + t * 256;          // 2048 float4s
            float4 e = eg[i];
            int r    = i >> 5;              // global row 0..63
            int j4   = i & 31;              // k-block of 4
            int rgA  = r >> 5;
            int mt   = (r >> 4) & 1;
            int rr   = r & 15;
            int ks   = j4 >> 1;
            int aidx = (rr >> 3) + ((j4 & 1) << 1);   // which of a0..a3
            int slot = (rgA * 2 + mt) * 16 + ks;
            int base = OFF_A + slot * 132 + (rr & 7) * 16 + aidx;
            sm[base + 0]  = to_tf32(e.x);
            sm[base + 4]  = to_tf32(e.y);
            sm[base + 8]  = to_tf32(e.z);
            sm[base + 12] = to_tf32(e.w);
        }
        if (tid < 64)
            sm[OFF_BIJ + tid] = weights[(size_t)(b0 + (tid >> 5)) * Ncap + (tid & 31)];
        __syncthreads();

        // ---- GEMM: each warp computes 32 rows (rg) x 64 cols (cg) ----
        float c[2][8][4];
        #pragma unroll
        for (int mt = 0; mt < 2; mt++)
            #pragma unroll
            for (int j = 0; j < 8; j++)
                #pragma unroll
                for (int q = 0; q < 4; q++) c[mt][j][q] = 0.0f;

        #pragma unroll
        for (int ks = 0; ks < 16; ks++) {
            float4 a0 = *(const float4*)&sm[OFF_A + ((rg * 2 + 0) * 16 + ks) * 132 + lane * 4];
            float4 a1 = *(const float4*)&sm[OFF_A + ((rg * 2 + 1) * 16 + ks) * 132 + lane * 4];
            #pragma unroll
            for (int j = 0; j < 8; j++) {
                float2 b = *(const float2*)&sm[OFF_W + (((cg * 8 + j) * 16 + ks) * 32 + lane) * 2];
                mma_tf32(c[0][j], a0, b);
                mma_tf32(c[1][j], a1, b);
            }
        }

        // ---- bias add + per-row squared-norm partials (fragment-resident) ----
        float pn[2][2] = {{0.f, 0.f}, {0.f, 0.f}};
        #pragma unroll
        for (int mt = 0; mt < 2; mt++)
            #pragma unroll
            for (int j = 0; j < 8; j++)
                #pragma unroll
                for (int q = 0; q < 4; q++) {
                    int p = q & 1, h = q >> 1;
                    int col = cg * 64 + j * 8 + qc * 2 + p;
                    float v = c[mt][j][q] + sm[OFF_BIAS + col];
                    c[mt][j][q] = v;
                    pn[mt][h] += v * v;
                }
        #pragma unroll
        for (int mt = 0; mt < 2; mt++)
            #pragma unroll
            for (int h = 0; h < 2; h++) {
                pn[mt][h] += __shfl_xor_sync(0xffffffffu, pn[mt][h], 1);
                pn[mt][h] += __shfl_xor_sync(0xffffffffu, pn[mt][h], 2);
            }
        if (qc == 0) {
            #pragma unroll
            for (int mt = 0; mt < 2; mt++)
                #pragma unroll
                for (int h = 0; h < 2; h++) {
                    int n = mt * 16 + qr + h * 8;
                    sm[OFF_NRM + rg * 128 + n * 4 + cg] = pn[mt][h];
                }
        }
        __syncthreads();
        if (tid < 64) {
            const float* p = &sm[OFF_NRM + (tid >> 5) * 128 + (tid & 31) * 4];
            float s   = p[0] + p[1] + p[2] + p[3];
            float nrm = sqrtf(s);
            sm[OFF_INV + tid] = 1.0f / fmaxf(nrm, 1e-12f);
        }
        __syncthreads();
        {
            float inv0 = sm[OFF_INV + rg * 32 + 0 * 16 + qr];
            float inv1 = sm[OFF_INV + rg * 32 + 0 * 16 + qr + 8];
            float inv2 = sm[OFF_INV + rg * 32 + 1 * 16 + qr];
            float inv3 = sm[OFF_INV + rg * 32 + 1 * 16 + qr + 8];
            #pragma unroll
            for (int j = 0; j < 8; j++) {
                c[0][j][0] *= inv0; c[0][j][1] *= inv0;
                c[0][j][2] *= inv1; c[0][j][3] *= inv1;
                c[1][j][0] *= inv2; c[1][j][1] *= inv2;
                c[1][j][2] *= inv3; c[1][j][3] *= inv3;
            }
        }

        // ---- dynamic routing (fragments stay in registers as u_hat) ----
        #pragma unroll 1
        for (int it = 0; it < RITERS; it++) {
            __syncthreads();  // b_ij visible / previous c_sm consumers done
            if (cg == 0) {    // warps 0 and 4 handle the two batches
                float bv = sm[OFF_BIJ + rg * 32 + lane];
                float m = bv;
                #pragma unroll
                for (int off = 16; off; off >>= 1)
                    m = fmaxf(m, __shfl_xor_sync(0xffffffffu, m, off));
                float e = expf(bv - m);
                float ssum = e;
                #pragma unroll
                for (int off = 16; off; off >>= 1)
                    ssum += __shfl_xor_sync(0xffffffffu, ssum, off);
                sm[OFF_C + rg * 32 + lane] = e * (32.0f / ssum);
            }
            __syncthreads();

            // s[d] = sum_n c[n] * u_hat[n][d], from fragments
            float cv0 = sm[OFF_C + rg * 32 + qr];
            float cv1 = sm[OFF_C + rg * 32 + qr + 8];
            float cv2 = sm[OFF_C + rg * 32 + 16 + qr];
            float cv3 = sm[OFF_C + rg * 32 + 16 + qr + 8];
            float sp[8][2];
            #pragma unroll
            for (int j = 0; j < 8; j++) {
                sp[j][0] = cv0 * c[0][j][0] + cv1 * c[0][j][2]
                         + cv2 * c[1][j][0] + cv3 * c[1][j][2];
                sp[j][1] = cv0 * c[0][j][1] + cv1 * c[0][j][3]
                         + cv2 * c[1][j][1] + cv3 * c[1][j][3];
            }
            #pragma unroll
            for (int j = 0; j < 8; j++)
                #pragma unroll
                for (int p = 0; p < 2; p++) {
                    sp[j][p] += __shfl_xor_sync(0xffffffffu, sp[j][p], 4);
                    sp[j][p] += __shfl_xor_sync(0xffffffffu, sp[j][p], 8);
                    sp[j][p] += __shfl_xor_sync(0xffffffffu, sp[j][p], 16);
                }
            if (qr == 0) {
                #pragma unroll
                for (int j = 0; j < 8; j++)
                    #pragma unroll
                    for (int p = 0; p < 2; p++)
                        sm[OFF_S + rg * 256 + cg * 64 + j * 8 + qc * 2 + p] = sp[j][p];
            }
            __syncthreads();

            // squash: block reduction of sum(s^2) per batch
            float x0 = sm[OFF_S + 0 * 256 + w * 32 + lane];
            float x1 = sm[OFF_S + 1 * 256 + w * 32 + lane];
            float q0 = x0 * x0, q1 = x1 * x1;
            #pragma unroll
            for (int off = 16; off; off >>= 1) {
                q0 += __shfl_xor_sync(0xffffffffu, q0, off);
                q1 += __shfl_xor_sync(0xffffffffu, q1, off);
            }
            if (lane == 0) {
                sm[OFF_SQP + w * 2 + 0] = q0;
                sm[OFF_SQP + w * 2 + 1] = q1;
            }
            __syncthreads();
            if (tid < 2) {
                float t = 0.0f;
                #pragma unroll
                for (int wi = 0; wi < 8; wi++) t += sm[OFF_SQP + wi * 2 + tid];
                sm[OFF_SC + tid] = t / ((1.0f + t) * sqrtf(t + 1e-9f));
            }
            __syncthreads();
            {
                float sc0 = sm[OFF_SC + 0], sc1 = sm[OFF_SC + 1];
                sm[OFF_V + tid]       = sc0 * sm[OFF_S + tid];
                sm[OFF_V + 256 + tid] = sc1 * sm[OFF_S + 256 + tid];
            }
            __syncthreads();

            if (it < RITERS - 1) {
                // agree[n] = dot(u_hat[n,:], v), from fragments
                float ap[2][2] = {{0.f, 0.f}, {0.f, 0.f}};
                #pragma unroll
                for (int mt = 0; mt < 2; mt++)
                    #pragma unroll
                    for (int j = 0; j < 8; j++) {
                        int colb = cg * 64 + j * 8 + qc * 2;
                        float v0 = sm[OFF_V + rg * 256 + colb];
                        float v1 = sm[OFF_V + rg * 256 + colb + 1];
                        ap[mt][0] += c[mt][j][0] * v0 + c[mt][j][1] * v1;
                        ap[mt][1] += c[mt][j][2] * v0 + c[mt][j][3] * v1;
                    }
                #pragma unroll
                for (int mt = 0; mt < 2; mt++)
                    #pragma unroll
                    for (int h = 0; h < 2; h++) {
                        ap[mt][h] += __shfl_xor_sync(0xffffffffu, ap[mt][h], 1);
                        ap[mt][h] += __shfl_xor_sync(0xffffffffu, ap[mt][h], 2);
                    }
                if (qc == 0) {
                    #pragma unroll
                    for (int mt = 0; mt < 2; mt++)
                        #pragma unroll
                        for (int h = 0; h < 2; h++) {
                            int n = mt * 16 + qr + h * 8;
                            sm[OFF_AGR + rg * 128 + n * 4 + cg] = ap[mt][h];
                        }
                }
                __syncthreads();
                if (tid < 64) {
                    const float* p = &sm[OFF_AGR + (tid >> 5) * 128 + (tid & 31) * 4];
                    sm[OFF_BIJ + tid] += p[0] + p[1] + p[2] + p[3];
                }
            }
        }

        // ---- outputs ----
        out_poses[(size_t)b0 * Dout + tid]       = sm[OFF_V + tid];
        out_poses[(size_t)(b0 + 1) * Dout + tid] = sm[OFF_V + 256 + tid];
        if (tid < 64)
            out_c[(size_t)(b0 + (tid >> 5)) * Ncap + (tid & 31)] = sm[OFF_C + tid];
    }
}

extern "C" void kernel_launch(void* const* d_in, const int* in_sizes, int n_in,
                              void* d_out, int out_size) {
    const float* embeds  = (const float*)d_in[0];
    const float* weights = (const float*)d_in[1];
    const float* Wg      = (const float*)d_in[2];
    const float* bg      = (const float*)d_in[3];
    float* out = (float*)d_out;

    cudaFuncSetAttribute(dyr_agg_kernel,
                         cudaFuncAttributeMaxDynamicSharedMemorySize, SMEM_BYTES);
    int sms = 148;
    cudaDeviceGetAttribute(&sms, cudaDevAttrMultiProcessorCount, 0);
    dyr_agg_kernel<<<sms, 256, SMEM_BYTES>>>(embeds, weights, Wg, bg, out);
}